// round 12
// baseline (speedup 1.0000x reference)
#include <cuda_runtime.h>
#include <cuda_fp16.h>
#include <math.h>
#include <stdint.h>

#define BSZ 64
#define SSZ 512
#define DSZ 1024
#define HSZ 1024
#define OFF_HN 33554432              // B*S*H
#define OFF_CN (33554432 + 65536)    // + B*H
#define NCTA 128

// ---------------- static device scratch (allocations are forbidden) --------
__device__ __half g_xp[(size_t)SSZ * BSZ * 4096];   // x_proj fp16 [t][b][4H], biases folded
__device__ __half g_xh[(size_t)BSZ * SSZ * DSZ];    // inputs fp16
__device__ __half g_wh[(size_t)4096 * DSZ];         // W_ih fp16
// hidden state in MMA-FRAGMENT layout, ping-pong:
//   u32 index = ((kc*4 + mt)*32 + lane)*4 + slot
//   kc=k>>4, mt=row>>4, lane=(row&7)*4+((k>>1)&3), slot=((k>>3)&1)*2+((row>>3)&1)
__device__ unsigned g_ht[2][64 * 4 * 32 * 4];
__device__ int g_gcnt[SSZ][8 * 32];  // 8 K-slice counters/step (128 warp arrivals)

// ---------------- helpers ---------------------------------------------------
__device__ __forceinline__ unsigned h2u(__half2 v) {
    return *reinterpret_cast<unsigned*>(&v);
}
__device__ __forceinline__ float fsigmoid(float x) {
    return 1.0f / (1.0f + __expf(-x));
}
__device__ __forceinline__ float ftanh(float x) {
    return 2.0f / (1.0f + __expf(-2.0f * x)) - 1.0f;
}
// fragment-layout u32 index for the half2 at (row, k), k even
__device__ __host__ __forceinline__ int ht_idx(int row, int k) {
    int kc = k >> 4, mt = row >> 4;
    int lane = (row & 7) * 4 + ((k >> 1) & 3);
    int slot = ((k >> 3) & 1) * 2 + ((row >> 3) & 1);
    return ((kc * 4 + mt) * 32 + lane) * 4 + slot;
}

#define MMA16816(c, a, b)                                                     \
    asm volatile(                                                             \
        "mma.sync.aligned.m16n8k16.row.col.f32.f16.f16.f32 "                  \
        "{%0,%1,%2,%3},{%4,%5,%6,%7},{%8,%9},{%0,%1,%2,%3};"                  \
        : "+f"((c)[0]), "+f"((c)[1]), "+f"((c)[2]), "+f"((c)[3])              \
        : "r"((a)[0]), "r"((a)[1]), "r"((a)[2]), "r"((a)[3]),                 \
          "r"((b)[0]), "r"((b)[1]))

#define CP_ASYNC16(dst, src)                                                  \
    asm volatile("cp.async.cg.shared.global [%0], [%1], 16;" ::               \
                 "r"(dst), "l"(src))
#define CP_COMMIT  asm volatile("cp.async.commit_group;")

template <int N>
__device__ __forceinline__ void cp_wait() {
    asm volatile("cp.async.wait_group %0;" :: "n"(N));
}

#define LDSM_X4(r0, r1, r2, r3, addr)                                         \
    asm volatile("ldmatrix.sync.aligned.m8n8.x4.shared.b16 "                  \
                 "{%0,%1,%2,%3}, [%4];"                                       \
                 : "=r"(r0), "=r"(r1), "=r"(r2), "=r"(r3) : "r"(addr))

// L1-bypassing 16B fragment load (ping-pong buffer: L1 is not coherent)
#define LDG128_CG(r0, r1, r2, r3, ptr)                                        \
    asm volatile("ld.global.cg.v4.b32 {%0,%1,%2,%3}, [%4];"                   \
                 : "=r"(r0), "=r"(r1), "=r"(r2), "=r"(r3) : "l"(ptr))

// conflict-free partials layout: [warp][gate][row(64)][col(8)] floats
#define GBW(w, g, row, col) ((((w) * 4 + (g)) * 64 + (row)) * 8 + (col))

// ---------------- phase 0: conversions + state init (grid-stride) ----------
__global__ void prep_kernel(const float* __restrict__ inp,
                            const float* __restrict__ h0,
                            const float* __restrict__ wih) {
    size_t tid = (size_t)blockIdx.x * blockDim.x + threadIdx.x;
    size_t nt = (size_t)gridDim.x * blockDim.x;

    const size_t n_inp4 = (size_t)BSZ * SSZ * DSZ / 4;
    for (size_t i = tid; i < n_inp4; i += nt) {
        float4 v = ((const float4*)inp)[i];
        ((__half2*)g_xh)[2 * i]     = __floats2half2_rn(v.x, v.y);
        ((__half2*)g_xh)[2 * i + 1] = __floats2half2_rn(v.z, v.w);
    }
    const size_t n_w4 = (size_t)4096 * DSZ / 4;
    for (size_t i = tid; i < n_w4; i += nt) {
        float4 v = ((const float4*)wih)[i];
        ((__half2*)g_wh)[2 * i]     = __floats2half2_rn(v.x, v.y);
        ((__half2*)g_wh)[2 * i + 1] = __floats2half2_rn(v.z, v.w);
    }
    // h0 into fragment layout
    const size_t n_h2 = (size_t)BSZ * HSZ / 2;
    for (size_t i = tid; i < n_h2; i += nt) {
        int row = (int)(i >> 9);
        int k = (int)(i & 511) * 2;
        float2 v = *(const float2*)&h0[row * 1024 + k];
        g_ht[0][ht_idx(row, k)] = h2u(__floats2half2_rn(v.x, v.y));
    }
    const size_t n_cnt = (size_t)SSZ * 8 * 32;
    for (size_t i = tid; i < n_cnt; i += nt) ((int*)g_gcnt)[i] = 0;
}

// ---------------- phase 1: x_proj = x @ Wih^T + bi + bh (fp16 out) ----------
__global__ __launch_bounds__(128) void xproj_kernel(
    const float* __restrict__ bi, const float* __restrict__ bh) {
    __shared__ __half smx[4 * 5120];   // As[2][128*40], Bs[2][128*40] = 40KB

    const int m0 = blockIdx.y * 128;
    const int n0 = blockIdx.x * 128;
    const int tid = threadIdx.x;
    const int warp = tid >> 5, lane = tid & 31;
    const int gid = lane >> 2, tig = lane & 3;
    const int rb = (warp & 1) * 64, cb = (warp >> 1) * 64;
    const unsigned sm_base = (unsigned)__cvta_generic_to_shared(smx);

    const int lrow = lane & 15;
    const int lkhi = (lane >> 4) * 8;
    const int brow = ((lane >> 4) * 8) + (lane & 7);
    const int bkhi = ((lane >> 3) & 1) * 8;

    float acc[4][8][4];
#pragma unroll
    for (int m = 0; m < 4; m++)
#pragma unroll
        for (int n = 0; n < 8; n++)
#pragma unroll
            for (int r = 0; r < 4; r++) acc[m][n][r] = 0.0f;

#define XSTAGE(buf, kb)                                                       \
    {                                                                         \
        _Pragma("unroll")                                                     \
        for (int i = 0; i < 4; i++) {                                         \
            int j = tid + i * 128;                                            \
            int row = j >> 2, q = j & 3;                                      \
            CP_ASYNC16(sm_base + ((buf) * 5120 + row * 40 + q * 8) * 2,       \
                       &g_xh[(size_t)(m0 + row) * 1024 + (kb) + q * 8]);      \
            CP_ASYNC16(sm_base + (10240 + (buf) * 5120 + row * 40 + q * 8) * 2,\
                       &g_wh[(size_t)(n0 + row) * 1024 + (kb) + q * 8]);      \
        }                                                                     \
        CP_COMMIT;                                                            \
    }

    XSTAGE(0, 0);
    for (int kbi = 0; kbi < 32; kbi++) {
        if (kbi < 31) {
            XSTAGE((kbi + 1) & 1, (kbi + 1) * 32);
            cp_wait<1>();
        } else {
            cp_wait<0>();
        }
        __syncthreads();
        const unsigned As = sm_base + (kbi & 1) * 5120 * 2;
        const unsigned Bs = sm_base + (10240 + (kbi & 1) * 5120) * 2;
#pragma unroll
        for (int ks = 0; ks < 32; ks += 16) {
            unsigned a[4][4], b[8][2];
#pragma unroll
            for (int m = 0; m < 4; m++) {
                unsigned addr = As +
                    (unsigned)((rb + m * 16 + lrow) * 40 + ks + lkhi) * 2;
                LDSM_X4(a[m][0], a[m][1], a[m][2], a[m][3], addr);
            }
#pragma unroll
            for (int p = 0; p < 4; p++) {
                unsigned addr = Bs +
                    (unsigned)((cb + p * 16 + brow) * 40 + ks + bkhi) * 2;
                LDSM_X4(b[2 * p][0], b[2 * p][1], b[2 * p + 1][0],
                        b[2 * p + 1][1], addr);
            }
#pragma unroll
            for (int m = 0; m < 4; m++)
#pragma unroll
                for (int n = 0; n < 8; n++) MMA16816(acc[m][n], a[m], b[n]);
        }
        __syncthreads();
    }

#pragma unroll
    for (int m = 0; m < 4; m++) {
#pragma unroll
        for (int n = 0; n < 8; n++) {
            int row = m0 + rb + m * 16 + gid;
            int col = n0 + cb + n * 8 + 2 * tig;
            float2 b1 = *(const float2*)&bi[col];
            float2 b2 = *(const float2*)&bh[col];
            float bs0 = b1.x + b2.x, bs1 = b1.y + b2.y;
            {
                int s = row & 511, bb = row >> 9;
                *(__half2*)&g_xp[(size_t)((s << 6) + bb) * 4096 + col] =
                    __floats2half2_rn(acc[m][n][0] + bs0, acc[m][n][1] + bs1);
            }
            {
                int r2 = row + 8;
                int s = r2 & 511, bb = r2 >> 9;
                *(__half2*)&g_xp[(size_t)((s << 6) + bb) * 4096 + col] =
                    __floats2half2_rn(acc[m][n][2] + bs0, acc[m][n][3] + bs1);
            }
        }
    }
}

// ---------------- phase 2: persistent recurrence ----------------------------
// 128 CTAs x 256 threads. CTA c owns h-cols [8c, 8c+8); 8 warps K-split.
// h lives in GLOBAL fragment layout: A-fragments load with ONE coalesced
// 16B LDG.cg per lane per (mt,s) — no smem staging, no ldmatrix.
__global__ __launch_bounds__(256) void lstm_rec_kernel(
    const float* __restrict__ c0, const float* __restrict__ Whh,
    float* __restrict__ out) {
    extern __shared__ float gb[];            // [8][4][64][8] floats = 65536 B

    const int cta = blockIdx.x;
    const int tid = threadIdx.x;
    const int warp = tid >> 5, lane = tid & 31;
    const int gid = lane >> 2, tig = lane & 3;
    const int K0 = warp * 128;
    const int hcb = cta * 8;

    // --- load W_hh fragments into registers (once) ---
    unsigned Breg[4][8][2];
#pragma unroll
    for (int g = 0; g < 4; g++) {
        const float* wr = Whh + (size_t)(g * 1024 + hcb + gid) * 1024 + K0;
#pragma unroll
        for (int s = 0; s < 8; s++) {
            int k = s * 16 + 2 * tig;
            Breg[g][s][0] = h2u(__floats2half2_rn(wr[k], wr[k + 1]));
            Breg[g][s][1] = h2u(__floats2half2_rn(wr[k + 8], wr[k + 9]));
        }
    }

    // --- elementwise ownership: row er, cols (hcb+ec, hcb+ec+1) ---
    const int er = tid >> 2;
    const int ec = (tid & 3) * 2;
    float cst[2];
    cst[0] = c0[er * 1024 + hcb + ec];
    cst[1] = c0[er * 1024 + hcb + ec + 1];

    // precomputed publish slot for this thread's half2 (row=er, k=hcb+ec)
    const int pub_idx = ht_idx(er, hcb + ec);

    // per-lane fragment base: byte offset of (kc = warp*8 + s, mt, lane)
    // addr = buf + ((kc*4 + mt)*32 + lane)*16
    const size_t frag_lane_off = (size_t)lane * 16;

#pragma unroll 1
    for (int t = 0; t < SSZ; t++) {
        const char* hb = (const char*)g_ht[t & 1];

        // prefetch x_proj gates (fp16, streaming; depends only on t)
        const __half* xp = g_xp + ((size_t)t * 64 + er) * 4096 + hcb + ec;
        float2 xg[4];
#pragma unroll
        for (int g = 0; g < 4; g++)
            xg[g] = __half22float2(__ldcs((const __half2*)(xp + g * 1024)));

        // --- group wait: all lanes acquire-poll (orders each lane's loads)
        if (t > 0) {
            const int* cp = &g_gcnt[t - 1][warp * 32];
            int v;
            asm volatile("ld.acquire.gpu.global.s32 %0, [%1];"
                         : "=r"(v) : "l"(cp) : "memory");
            while (v < 128) {
                __nanosleep(32);
                asm volatile("ld.acquire.gpu.global.s32 %0, [%1];"
                             : "=r"(v) : "l"(cp) : "memory");
            }
        }

        // --- MMA: fragment LDGs double-buffered across m-tiles ---
        float acc[4][4][4];
#pragma unroll
        for (int m = 0; m < 4; m++)
#pragma unroll
            for (int g = 0; g < 4; g++)
#pragma unroll
                for (int r = 0; r < 4; r++) acc[m][g][r] = 0.0f;

        unsigned af[2][8][4];
#pragma unroll
        for (int s = 0; s < 8; s++) {
            const char* p = hb + ((size_t)((warp * 8 + s) * 4 + 0) * 512) +
                            frag_lane_off;
            LDG128_CG(af[0][s][0], af[0][s][1], af[0][s][2], af[0][s][3], p);
        }
#pragma unroll
        for (int mt = 0; mt < 4; mt++) {
            if (mt < 3) {
#pragma unroll
                for (int s = 0; s < 8; s++) {
                    const char* p = hb +
                        ((size_t)((warp * 8 + s) * 4 + (mt + 1)) * 512) +
                        frag_lane_off;
                    LDG128_CG(af[(mt + 1) & 1][s][0], af[(mt + 1) & 1][s][1],
                              af[(mt + 1) & 1][s][2], af[(mt + 1) & 1][s][3], p);
                }
            }
#pragma unroll
            for (int s = 0; s < 8; s++)
#pragma unroll
                for (int g = 0; g < 4; g++)
                    MMA16816(acc[mt][g], af[mt & 1][s], Breg[g][s]);
        }

        // --- single-phase K reduction: conflict-free layout ---
#pragma unroll
        for (int m = 0; m < 4; m++)
#pragma unroll
            for (int g = 0; g < 4; g++) {
                int r0 = m * 16 + gid;
                *(float2*)&gb[GBW(warp, g, r0, 2 * tig)] =
                    make_float2(acc[m][g][0], acc[m][g][1]);
                *(float2*)&gb[GBW(warp, g, r0 + 8, 2 * tig)] =
                    make_float2(acc[m][g][2], acc[m][g][3]);
            }
        __syncthreads();

        // --- elementwise LSTM cell for (er, ec), (er, ec+1) ---
        float2 gate2[4];
#pragma unroll
        for (int g = 0; g < 4; g++) {
            float2 v = xg[g];
#pragma unroll
            for (int w = 0; w < 8; w++) {
                float2 pv = *(const float2*)&gb[GBW(w, g, er, ec)];
                v.x += pv.x;
                v.y += pv.y;
            }
            gate2[g] = v;
        }

        float hres[2];
#pragma unroll
        for (int j = 0; j < 2; j++) {
            float gi = j ? gate2[0].y : gate2[0].x;
            float gf = j ? gate2[1].y : gate2[1].x;
            float gg = j ? gate2[2].y : gate2[2].x;
            float go = j ? gate2[3].y : gate2[3].x;
            float i_ = fsigmoid(gi);
            float f_ = fsigmoid(gf);
            float g_ = ftanh(gg);
            float o_ = fsigmoid(go);
            float cn = f_ * cst[j] + i_ * g_;
            cst[j] = cn;
            hres[j] = o_ * ftanh(cn);
        }

        if (t < SSZ - 1) {
            // publish next-step h fragment (one u32), then per-warp arrive
            g_ht[(t + 1) & 1][pub_idx] = h2u(__floats2half2_rn(hres[0], hres[1]));
            __syncwarp();
            if (lane == 0) {
                asm volatile("red.release.gpu.global.add.s32 [%0], 1;"
                             :: "l"(&g_gcnt[t][(cta >> 4) * 32]) : "memory");
            }
            // out store (streaming) in arrival shadow
            __stcs((float2*)&out[((size_t)er * 512 + t) * 1024 + hcb + ec],
                   make_float2(hres[0], hres[1]));
            __syncthreads();   // gb read-complete before next step's writes
        } else {
            __stcs((float2*)&out[((size_t)er * 512 + t) * 1024 + hcb + ec],
                   make_float2(hres[0], hres[1]));
            *(float2*)&out[OFF_HN + er * 1024 + hcb + ec] =
                make_float2(hres[0], hres[1]);
            *(float2*)&out[OFF_CN + er * 1024 + hcb + ec] =
                make_float2(cst[0], cst[1]);
        }
    }
}

// ---------------- launch -----------------------------------------------------
extern "C" void kernel_launch(void* const* d_in, const int* in_sizes, int n_in,
                              void* d_out, int out_size) {
    const float* inp = (const float*)d_in[0];
    const float* h0  = (const float*)d_in[1];
    const float* c0  = (const float*)d_in[2];
    const float* wih = (const float*)d_in[3];
    const float* whh = (const float*)d_in[4];
    const float* bih = (const float*)d_in[5];
    const float* bhh = (const float*)d_in[6];
    float* out = (float*)d_out;

    const int rec_smem = 8 * 4 * 64 * 8 * 4;  // 65536 B
    cudaFuncSetAttribute(lstm_rec_kernel,
                         cudaFuncAttributeMaxDynamicSharedMemorySize, rec_smem);

    prep_kernel<<<2048, 256>>>(inp, h0, wih);
    dim3 g1(32, 256);
    xproj_kernel<<<g1, 128>>>(bih, bhh);
    lstm_rec_kernel<<<NCTA, 256, rec_smem>>>(c0, whh, out);
}

// round 13
// speedup vs baseline: 1.1498x; 1.1498x over previous
#include <cuda_runtime.h>
#include <cuda_fp16.h>
#include <math.h>
#include <stdint.h>

#define BSZ 64
#define SSZ 512
#define DSZ 1024
#define HSZ 1024
#define OFF_HN 33554432              // B*S*H
#define OFF_CN (33554432 + 65536)    // + B*H
#define NCTA 128
#define HPAD 1032                    // h smem row stride (halves): 4-word shift/row

// ---------------- static device scratch (allocations are forbidden) --------
__device__ __half g_xp[(size_t)SSZ * BSZ * 4096];   // x_proj fp16 [t][b][4H], biases folded
__device__ __half g_xh[(size_t)BSZ * SSZ * DSZ];    // inputs fp16
__device__ __half g_wh[(size_t)4096 * DSZ];         // W_ih fp16
__device__ __half g_h[2][BSZ * HSZ];                // ping-pong hidden state fp16
__device__ int    g_gcnt[SSZ][8 * 32];              // 8 K-slice counters/step (128 warp arrivals)

// ---------------- helpers ---------------------------------------------------
__device__ __forceinline__ unsigned h2u(__half2 v) {
    return *reinterpret_cast<unsigned*>(&v);
}
__device__ __forceinline__ float fsigmoid(float x) {
    return 1.0f / (1.0f + __expf(-x));
}
__device__ __forceinline__ float ftanh(float x) {
    return 2.0f / (1.0f + __expf(-2.0f * x)) - 1.0f;
}

#define MMA16816(c, a, b)                                                     \
    asm volatile(                                                             \
        "mma.sync.aligned.m16n8k16.row.col.f32.f16.f16.f32 "                  \
        "{%0,%1,%2,%3},{%4,%5,%6,%7},{%8,%9},{%0,%1,%2,%3};"                  \
        : "+f"((c)[0]), "+f"((c)[1]), "+f"((c)[2]), "+f"((c)[3])              \
        : "r"((a)[0]), "r"((a)[1]), "r"((a)[2]), "r"((a)[3]),                 \
          "r"((b)[0]), "r"((b)[1]))

#define CP_ASYNC16(dst, src)                                                  \
    asm volatile("cp.async.cg.shared.global [%0], [%1], 16;" ::               \
                 "r"(dst), "l"(src))
#define CP_COMMIT  asm volatile("cp.async.commit_group;")

template <int N>
__device__ __forceinline__ void cp_wait() {
    asm volatile("cp.async.wait_group %0;" :: "n"(N));
}

#define LDSM_X4(r0, r1, r2, r3, addr)                                         \
    asm volatile("ldmatrix.sync.aligned.m8n8.x4.shared.b16 "                  \
                 "{%0,%1,%2,%3}, [%4];"                                       \
                 : "=r"(r0), "=r"(r1), "=r"(r2), "=r"(r3) : "r"(addr))

// fp16 partials layout: [buf][warp][gate][row(64)][col(8)] halves
#define GBW(w, g, row, col) ((((w) * 4 + (g)) * 64 + (row)) * 8 + (col))

// ---------------- phase 0: conversions + state init (grid-stride) ----------
__global__ void prep_kernel(const float* __restrict__ inp,
                            const float* __restrict__ h0,
                            const float* __restrict__ wih) {
    size_t tid = (size_t)blockIdx.x * blockDim.x + threadIdx.x;
    size_t nt = (size_t)gridDim.x * blockDim.x;

    const size_t n_inp4 = (size_t)BSZ * SSZ * DSZ / 4;
    for (size_t i = tid; i < n_inp4; i += nt) {
        float4 v = ((const float4*)inp)[i];
        ((__half2*)g_xh)[2 * i]     = __floats2half2_rn(v.x, v.y);
        ((__half2*)g_xh)[2 * i + 1] = __floats2half2_rn(v.z, v.w);
    }
    const size_t n_w4 = (size_t)4096 * DSZ / 4;
    for (size_t i = tid; i < n_w4; i += nt) {
        float4 v = ((const float4*)wih)[i];
        ((__half2*)g_wh)[2 * i]     = __floats2half2_rn(v.x, v.y);
        ((__half2*)g_wh)[2 * i + 1] = __floats2half2_rn(v.z, v.w);
    }
    const size_t n_h4 = (size_t)BSZ * HSZ / 4;
    for (size_t i = tid; i < n_h4; i += nt) {
        float4 v = ((const float4*)h0)[i];
        ((__half2*)g_h[0])[2 * i]     = __floats2half2_rn(v.x, v.y);
        ((__half2*)g_h[0])[2 * i + 1] = __floats2half2_rn(v.z, v.w);
    }
    const size_t n_cnt = (size_t)SSZ * 8 * 32;
    for (size_t i = tid; i < n_cnt; i += nt) ((int*)g_gcnt)[i] = 0;
}

// ---------------- phase 1: x_proj = x @ Wih^T + bi + bh (fp16 out) ----------
__global__ __launch_bounds__(128) void xproj_kernel(
    const float* __restrict__ bi, const float* __restrict__ bh) {
    __shared__ __half smx[4 * 5120];   // As[2][128*40], Bs[2][128*40] = 40KB

    const int m0 = blockIdx.y * 128;
    const int n0 = blockIdx.x * 128;
    const int tid = threadIdx.x;
    const int warp = tid >> 5, lane = tid & 31;
    const int gid = lane >> 2, tig = lane & 3;
    const int rb = (warp & 1) * 64, cb = (warp >> 1) * 64;
    const unsigned sm_base = (unsigned)__cvta_generic_to_shared(smx);

    const int lrow = lane & 15;
    const int lkhi = (lane >> 4) * 8;
    const int brow = ((lane >> 4) * 8) + (lane & 7);
    const int bkhi = ((lane >> 3) & 1) * 8;

    float acc[4][8][4];
#pragma unroll
    for (int m = 0; m < 4; m++)
#pragma unroll
        for (int n = 0; n < 8; n++)
#pragma unroll
            for (int r = 0; r < 4; r++) acc[m][n][r] = 0.0f;

#define XSTAGE(buf, kb)                                                       \
    {                                                                         \
        _Pragma("unroll")                                                     \
        for (int i = 0; i < 4; i++) {                                         \
            int j = tid + i * 128;                                            \
            int row = j >> 2, q = j & 3;                                      \
            CP_ASYNC16(sm_base + ((buf) * 5120 + row * 40 + q * 8) * 2,       \
                       &g_xh[(size_t)(m0 + row) * 1024 + (kb) + q * 8]);      \
            CP_ASYNC16(sm_base + (10240 + (buf) * 5120 + row * 40 + q * 8) * 2,\
                       &g_wh[(size_t)(n0 + row) * 1024 + (kb) + q * 8]);      \
        }                                                                     \
        CP_COMMIT;                                                            \
    }

    XSTAGE(0, 0);
    for (int kbi = 0; kbi < 32; kbi++) {
        if (kbi < 31) {
            XSTAGE((kbi + 1) & 1, (kbi + 1) * 32);
            cp_wait<1>();
        } else {
            cp_wait<0>();
        }
        __syncthreads();
        const unsigned As = sm_base + (kbi & 1) * 5120 * 2;
        const unsigned Bs = sm_base + (10240 + (kbi & 1) * 5120) * 2;
#pragma unroll
        for (int ks = 0; ks < 32; ks += 16) {
            unsigned a[4][4], b[8][2];
#pragma unroll
            for (int m = 0; m < 4; m++) {
                unsigned addr = As +
                    (unsigned)((rb + m * 16 + lrow) * 40 + ks + lkhi) * 2;
                LDSM_X4(a[m][0], a[m][1], a[m][2], a[m][3], addr);
            }
#pragma unroll
            for (int p = 0; p < 4; p++) {
                unsigned addr = Bs +
                    (unsigned)((cb + p * 16 + brow) * 40 + ks + bkhi) * 2;
                LDSM_X4(b[2 * p][0], b[2 * p][1], b[2 * p + 1][0],
                        b[2 * p + 1][1], addr);
            }
#pragma unroll
            for (int m = 0; m < 4; m++)
#pragma unroll
                for (int n = 0; n < 8; n++) MMA16816(acc[m][n], a[m], b[n]);
        }
        __syncthreads();
    }

#pragma unroll
    for (int m = 0; m < 4; m++) {
#pragma unroll
        for (int n = 0; n < 8; n++) {
            int row = m0 + rb + m * 16 + gid;
            int col = n0 + cb + n * 8 + 2 * tig;
            float2 b1 = *(const float2*)&bi[col];
            float2 b2 = *(const float2*)&bh[col];
            float bs0 = b1.x + b2.x, bs1 = b1.y + b2.y;
            {
                int s = row & 511, bb = row >> 9;
                *(__half2*)&g_xp[(size_t)((s << 6) + bb) * 4096 + col] =
                    __floats2half2_rn(acc[m][n][0] + bs0, acc[m][n][1] + bs1);
            }
            {
                int r2 = row + 8;
                int s = r2 & 511, bb = r2 >> 9;
                *(__half2*)&g_xp[(size_t)((s << 6) + bb) * 4096 + col] =
                    __floats2half2_rn(acc[m][n][2] + bs0, acc[m][n][3] + bs1);
            }
        }
    }
}

// ---------------- phase 2: persistent recurrence ----------------------------
// 128 CTAs x 256 threads. CTA c owns h-cols [8c, 8c+8); 8 warps K-split.
// cp.async staging + LDSM (best-known core). fp16 gate partials double-
// buffered: ONE CTA-wide sync per step. Per-warp group barrier.
__global__ __launch_bounds__(256) void lstm_rec_kernel(
    const float* __restrict__ c0, const float* __restrict__ Whh,
    float* __restrict__ out) {
    extern __shared__ __half sm[];
    __half* Hs = sm;                          // [64][HPAD] halves = 132096 B
    __half* gbh = sm + 64 * HPAD;             // [2][8][4][64][8] halves = 65536 B
    const unsigned hs_base = (unsigned)__cvta_generic_to_shared(Hs);

    const int cta = blockIdx.x;
    const int tid = threadIdx.x;
    const int warp = tid >> 5, lane = tid & 31;
    const int gid = lane >> 2, tig = lane & 3;
    const int K0 = warp * 128;
    const int hcb = cta * 8;

    const int lrow = lane & 15;              // ldmatrix row within m16 tile
    const int lkhi = (lane >> 4) * 8;        // ldmatrix k offset 0/8
    const int sr2 = lane >> 4;               // staging: row parity within pair
    const int sc16 = lane & 15;              // staging: 16B chunk within 256B

    // --- load W_hh fragments into registers (once) ---
    unsigned Breg[4][8][2];
#pragma unroll
    for (int g = 0; g < 4; g++) {
        const float* wr = Whh + (size_t)(g * 1024 + hcb + gid) * 1024 + K0;
#pragma unroll
        for (int s = 0; s < 8; s++) {
            int k = s * 16 + 2 * tig;
            Breg[g][s][0] = h2u(__floats2half2_rn(wr[k], wr[k + 1]));
            Breg[g][s][1] = h2u(__floats2half2_rn(wr[k + 8], wr[k + 9]));
        }
    }

    // --- elementwise ownership: row er, cols (hcb+ec, hcb+ec+1) ---
    const int er = tid >> 2;
    const int ec = (tid & 3) * 2;
    float cst[2];
    cst[0] = c0[er * 1024 + hcb + ec];
    cst[1] = c0[er * 1024 + hcb + ec + 1];

#pragma unroll 1
    for (int t = 0; t < SSZ; t++) {
        const __half* hb = g_h[t & 1];
        __half* gbuf = gbh + (t & 1) * 16384;

        // prefetch x_proj gates (fp16, streaming; depends only on t)
        const __half* xp = g_xp + ((size_t)t * 64 + er) * 4096 + hcb + ec;
        float2 xg[4];
#pragma unroll
        for (int g = 0; g < 4; g++)
            xg[g] = __half22float2(__ldcs((const __half2*)(xp + g * 1024)));

        // --- per-warp group wait (128 warp-arrivals), nanosleep backoff ---
        if (t > 0) {
            if (lane == 0) {
                int v;
                asm volatile("ld.acquire.gpu.global.s32 %0, [%1];"
                             : "=r"(v) : "l"(&g_gcnt[t - 1][warp * 32])
                             : "memory");
                while (v < 128) {
                    __nanosleep(32);
                    asm volatile("ld.acquire.gpu.global.s32 %0, [%1];"
                                 : "=r"(v) : "l"(&g_gcnt[t - 1][warp * 32])
                                 : "memory");
                }
            }
            __syncwarp();
        }

        // --- stage own K-slice: 4 groups (16 rows each), contiguous instrs
#pragma unroll
        for (int mt = 0; mt < 4; mt++) {
#pragma unroll
            for (int i = 0; i < 8; i++) {
                int row = mt * 16 + 2 * i + sr2;
                CP_ASYNC16(hs_base + (unsigned)(row * HPAD + K0 + sc16 * 8) * 2,
                           hb + row * 1024 + K0 + sc16 * 8);
            }
            CP_COMMIT;
        }

        // --- MMA: m-outer with rolling group waits ---
        float acc[4][4][4];
#pragma unroll
        for (int m = 0; m < 4; m++)
#pragma unroll
            for (int g = 0; g < 4; g++)
#pragma unroll
                for (int r = 0; r < 4; r++) acc[m][g][r] = 0.0f;

#pragma unroll
        for (int mt = 0; mt < 4; mt++) {
            switch (mt) {
                case 0: cp_wait<3>(); break;
                case 1: cp_wait<2>(); break;
                case 2: cp_wait<1>(); break;
                case 3: cp_wait<0>(); break;
            }
#pragma unroll
            for (int s = 0; s < 8; s++) {
                unsigned a[4];
                unsigned addr = hs_base +
                    (unsigned)((mt * 16 + lrow) * HPAD + K0 + s * 16 + lkhi) * 2;
                LDSM_X4(a[0], a[1], a[2], a[3], addr);
#pragma unroll
                for (int g = 0; g < 4; g++) MMA16816(acc[mt][g], a, Breg[g][s]);
            }
        }

        // --- K reduction: fp16 partials, conflict-free, ONE sync ---
#pragma unroll
        for (int m = 0; m < 4; m++)
#pragma unroll
            for (int g = 0; g < 4; g++) {
                int r0 = m * 16 + gid;
                *(__half2*)&gbuf[GBW(warp, g, r0, 2 * tig)] =
                    __floats2half2_rn(acc[m][g][0], acc[m][g][1]);
                *(__half2*)&gbuf[GBW(warp, g, r0 + 8, 2 * tig)] =
                    __floats2half2_rn(acc[m][g][2], acc[m][g][3]);
            }
        __syncthreads();

        // --- elementwise LSTM cell for (er, ec), (er, ec+1) ---
        float2 gate2[4];
#pragma unroll
        for (int g = 0; g < 4; g++) {
            float2 v = xg[g];
#pragma unroll
            for (int w = 0; w < 8; w++) {
                float2 pv =
                    __half22float2(*(const __half2*)&gbuf[GBW(w, g, er, ec)]);
                v.x += pv.x;
                v.y += pv.y;
            }
            gate2[g] = v;
        }

        float hres[2];
#pragma unroll
        for (int j = 0; j < 2; j++) {
            float gi = j ? gate2[0].y : gate2[0].x;
            float gf = j ? gate2[1].y : gate2[1].x;
            float gg = j ? gate2[2].y : gate2[2].x;
            float go = j ? gate2[3].y : gate2[3].x;
            float i_ = fsigmoid(gi);
            float f_ = fsigmoid(gf);
            float g_ = ftanh(gg);
            float o_ = fsigmoid(go);
            float cn = f_ * cst[j] + i_ * g_;
            cst[j] = cn;
            hres[j] = o_ * ftanh(cn);
        }

        if (t < SSZ - 1) {
            // per-warp publish + arrive; no trailing CTA sync (gb double-buffered)
            *(__half2*)&g_h[(t + 1) & 1][er * 1024 + hcb + ec] =
                __floats2half2_rn(hres[0], hres[1]);
            __syncwarp();
            if (lane == 0) {
                asm volatile("red.release.gpu.global.add.s32 [%0], 1;"
                             :: "l"(&g_gcnt[t][(cta >> 4) * 32]) : "memory");
            }
            __stcs((float2*)&out[((size_t)er * 512 + t) * 1024 + hcb + ec],
                   make_float2(hres[0], hres[1]));
        } else {
            __stcs((float2*)&out[((size_t)er * 512 + t) * 1024 + hcb + ec],
                   make_float2(hres[0], hres[1]));
            *(float2*)&out[OFF_HN + er * 1024 + hcb + ec] =
                make_float2(hres[0], hres[1]);
            *(float2*)&out[OFF_CN + er * 1024 + hcb + ec] =
                make_float2(cst[0], cst[1]);
        }
    }
}

// ---------------- launch -----------------------------------------------------
extern "C" void kernel_launch(void* const* d_in, const int* in_sizes, int n_in,
                              void* d_out, int out_size) {
    const float* inp = (const float*)d_in[0];
    const float* h0  = (const float*)d_in[1];
    const float* c0  = (const float*)d_in[2];
    const float* wih = (const float*)d_in[3];
    const float* whh = (const float*)d_in[4];
    const float* bih = (const float*)d_in[5];
    const float* bhh = (const float*)d_in[6];
    float* out = (float*)d_out;

    const int rec_smem = 64 * HPAD * 2 + 2 * 8 * 4 * 64 * 8 * 2;  // 197632 B
    cudaFuncSetAttribute(lstm_rec_kernel,
                         cudaFuncAttributeMaxDynamicSharedMemorySize, rec_smem);

    prep_kernel<<<2048, 256>>>(inp, h0, wih);
    dim3 g1(32, 256);
    xproj_kernel<<<g1, 128>>>(bih, bhh);
    lstm_rec_kernel<<<NCTA, 256, rec_smem>>>(c0, whh, out);
}